// round 4
// baseline (speedup 1.0000x reference)
#include <cuda_runtime.h>
#include <math.h>

#define BATCH   2048
#define IN_DIM  376
#define HID     1024
#define NOUT    17
#define NCELLS  6
#define NOPS    5

#define BM 128
#define BN 64
#define BK 16
#define TM 8
#define TN 4
#define NTHREADS 256

// scratch: acc buffers for nodes 1..5 (index i-1), plus softmax weights
__device__ float g_acc[5u * BATCH * HID];
__device__ float g_z[5 * 6 * 5];

typedef unsigned long long u64;

__device__ __forceinline__ u64 pack2(float lo, float hi) {
    u64 r; asm("mov.b64 %0, {%1, %2};" : "=l"(r) : "f"(lo), "f"(hi)); return r;
}
__device__ __forceinline__ void unpack2(u64 v, float& lo, float& hi) {
    asm("mov.b64 {%0, %1}, %2;" : "=f"(lo), "=f"(hi) : "l"(v));
}
// packed dual-FMA: (d.lo, d.hi) = (a.lo*b.lo+c.lo, a.hi*b.hi+c.hi)
__device__ __forceinline__ u64 ffma2(u64 a, u64 b, u64 c) {
    u64 d; asm("fma.rn.f32x2 %0, %1, %2, %3;" : "=l"(d) : "l"(a), "l"(b), "l"(c)); return d;
}

// ---------------------------------------------------------------------------
// z = softmax((log_alphas + eps) / TAU) over the op axis. TAU = 1.
// ---------------------------------------------------------------------------
__global__ void z_kernel(const float* __restrict__ la, const float* __restrict__ eps) {
    int t = threadIdx.x;
    if (t < 30) {
        const float* a = la  + t * NOPS;
        const float* e = eps + t * NOPS;
        float v[NOPS], mx = -1e30f;
        #pragma unroll
        for (int o = 0; o < NOPS; o++) { v[o] = a[o] + e[o]; mx = fmaxf(mx, v[o]); }
        float s = 0.f;
        #pragma unroll
        for (int o = 0; o < NOPS; o++) { v[o] = expf(v[o] - mx); s += v[o]; }
        float inv = 1.f / s;
        #pragma unroll
        for (int o = 0; o < NOPS; o++) g_z[t * NOPS + o] = v[o] * inv;
    }
}

// op order: 0=Tanh, 1=ReLU, 2=ELU, 3=LeakyReLU(0.01). Op 4 (NullOp) == 0, skipped.
__device__ __forceinline__ float actf(int o, float v) {
    switch (o) {
        case 0:  return tanhf(v);
        case 1:  return fmaxf(v, 0.f);
        case 2:  return v > 0.f ? v : expm1f(v);
        default: return v > 0.f ? v : 0.01f * v;
    }
}

// ---------------------------------------------------------------------------
// Stage kernel: source node `stage` feeds targets i = stage+1 .. 5.
// Each CTA: one (target, 128x64 tile); computes 4 op-GEMM tiles sharing the A
// tile, then epilogue: act + z-weight + accumulate into g_acc[target-1].
// grid = (BATCH/BM, HID/BN, 5-stage)
// ---------------------------------------------------------------------------
__global__ __launch_bounds__(NTHREADS, 1)
void stage_kernel(int stage, const float* __restrict__ x,
                  const float* __restrict__ W0, const float* __restrict__ b0,
                  const float* __restrict__ Wh, const float* __restrict__ bh)
{
    const int i = stage + 1 + blockIdx.z;   // target node (1..5)
    const float* A; int Kd;
    const float* W; const float* bias;
    if (stage == 0) {
        A = x; Kd = IN_DIM;
        W    = W0 + (size_t)(i * NOPS) * IN_DIM * HID;
        bias = b0 + (size_t)(i * NOPS) * HID;
    } else {
        A = g_acc + (size_t)(stage - 1) * BATCH * HID; Kd = HID;
        W    = Wh + (size_t)(((stage - 1) * NCELLS + i) * NOPS) * HID * HID;
        bias = bh + (size_t)(((stage - 1) * NCELLS + i) * NOPS) * HID;
    }
    float* accOut = g_acc + (size_t)(i - 1) * BATCH * HID;
    const float* zp = g_z + (stage * NCELLS + i) * NOPS;

    __shared__ __align__(16) float As[2][BK][BM];        // transposed A tile
    __shared__ __align__(16) float Bs[2][4][BK][BN];     // 4 op weight tiles

    const int tid = threadIdx.x;
    const int tx  = tid & 15;     // n micro index
    const int ty  = tid >> 4;     // m micro index
    const int bm0 = blockIdx.x * BM;
    const int bn0 = blockIdx.y * BN;

    u64 acc[4][TM][2];
    #pragma unroll
    for (int o = 0; o < 4; o++)
        #pragma unroll
        for (int m = 0; m < TM; m++) { acc[o][m][0] = 0ull; acc[o][m][1] = 0ull; }

    const int nk = (Kd + BK - 1) / BK;

    // global-load thread mapping
    const int ar  = tid >> 2;          // A: row 0..63 (+64 for second half)
    const int ac4 = (tid & 3) * 4;     // A: k offset within tile
    const int br  = tid >> 4;          // B: k row 0..15
    const int bn4 = (tid & 15) * 4;    // B: n offset

    float4 aR[2]; float4 bR[4];

    auto loadG = [&](int kt) {
        const int k0 = kt * BK;
        #pragma unroll
        for (int h = 0; h < 2; h++) {
            int row = ar + h * 64;
            int gk  = k0 + ac4;
            aR[h] = (gk + 4 <= Kd)
                ? *reinterpret_cast<const float4*>(A + (size_t)(bm0 + row) * Kd + gk)
                : make_float4(0.f, 0.f, 0.f, 0.f);
        }
        int gkb = k0 + br;
        #pragma unroll
        for (int o = 0; o < 4; o++) {
            bR[o] = (gkb < Kd)
                ? *reinterpret_cast<const float4*>(W + (size_t)o * Kd * HID + (size_t)gkb * HID + bn0 + bn4)
                : make_float4(0.f, 0.f, 0.f, 0.f);
        }
    };
    auto stS = [&](int buf) {
        #pragma unroll
        for (int h = 0; h < 2; h++) {
            int row = ar + h * 64;
            As[buf][ac4 + 0][row] = aR[h].x;
            As[buf][ac4 + 1][row] = aR[h].y;
            As[buf][ac4 + 2][row] = aR[h].z;
            As[buf][ac4 + 3][row] = aR[h].w;
        }
        #pragma unroll
        for (int o = 0; o < 4; o++)
            *reinterpret_cast<float4*>(&Bs[buf][o][br][bn4]) = bR[o];
    };

    loadG(0);
    stS(0);
    __syncthreads();

    for (int kt = 0; kt < nk; kt++) {
        const int cur = kt & 1;
        const bool more = (kt + 1 < nk);
        if (more) loadG(kt + 1);

        #pragma unroll
        for (int kk = 0; kk < BK; kk++) {
            float4 alo = *reinterpret_cast<const float4*>(&As[cur][kk][ty * TM]);
            float4 ahi = *reinterpret_cast<const float4*>(&As[cur][kk][ty * TM + 4]);
            u64 am[TM];
            am[0] = pack2(alo.x, alo.x); am[1] = pack2(alo.y, alo.y);
            am[2] = pack2(alo.z, alo.z); am[3] = pack2(alo.w, alo.w);
            am[4] = pack2(ahi.x, ahi.x); am[5] = pack2(ahi.y, ahi.y);
            am[6] = pack2(ahi.z, ahi.z); am[7] = pack2(ahi.w, ahi.w);
            #pragma unroll
            for (int o = 0; o < 4; o++) {
                const u64* bp = reinterpret_cast<const u64*>(&Bs[cur][o][kk][tx * TN]);
                u64 b01 = bp[0], b23 = bp[1];
                #pragma unroll
                for (int m = 0; m < TM; m++) {
                    acc[o][m][0] = ffma2(am[m], b01, acc[o][m][0]);
                    acc[o][m][1] = ffma2(am[m], b23, acc[o][m][1]);
                }
            }
        }
        if (more) { stS(cur ^ 1); __syncthreads(); }
    }

    // epilogue: bias + activation + z-weighted sum over ops, accumulate
    float zv[4];
    #pragma unroll
    for (int o = 0; o < 4; o++) zv[o] = zp[o];

    const int gn = bn0 + tx * TN;
    float4 bfr[4];
    #pragma unroll
    for (int o = 0; o < 4; o++)
        bfr[o] = *reinterpret_cast<const float4*>(bias + (size_t)o * HID + gn);

    #pragma unroll
    for (int m = 0; m < TM; m++) {
        const int gm = bm0 + ty * TM + m;
        float s0 = 0.f, s1 = 0.f, s2 = 0.f, s3 = 0.f;
        #pragma unroll
        for (int o = 0; o < 4; o++) {
            float p0, p1, p2, p3;
            unpack2(acc[o][m][0], p0, p1);
            unpack2(acc[o][m][1], p2, p3);
            p0 += bfr[o].x; p1 += bfr[o].y; p2 += bfr[o].z; p3 += bfr[o].w;
            s0 += zv[o] * actf(o, p0);
            s1 += zv[o] * actf(o, p1);
            s2 += zv[o] * actf(o, p2);
            s3 += zv[o] * actf(o, p3);
        }
        float* dst = accOut + (size_t)gm * HID + gn;
        float4 res = make_float4(s0, s1, s2, s3);
        if (stage != 0) {
            float4 old = *reinterpret_cast<const float4*>(dst);
            res.x += old.x; res.y += old.y; res.z += old.z; res.w += old.w;
        }
        *reinterpret_cast<float4*>(dst) = res;
    }
}

// ---------------------------------------------------------------------------
// out = tanh(acc5 @ Wout + bout); one warp per batch row, 17 outputs.
// ---------------------------------------------------------------------------
__global__ void out_kernel(const float* __restrict__ Wout,
                           const float* __restrict__ bout,
                           float* __restrict__ out)
{
    const int gw   = (blockIdx.x * blockDim.x + threadIdx.x) >> 5;
    const int lane = threadIdx.x & 31;
    if (gw >= BATCH) return;
    const float* a = g_acc + (size_t)4 * BATCH * HID + (size_t)gw * HID;

    float s[NOUT];
    #pragma unroll
    for (int n = 0; n < NOUT; n++) s[n] = 0.f;

    for (int kk = lane; kk < HID; kk += 32) {
        float av = a[kk];
        const float* wr = Wout + (size_t)kk * NOUT;
        #pragma unroll
        for (int n = 0; n < NOUT; n++) s[n] = fmaf(av, wr[n], s[n]);
    }
    #pragma unroll
    for (int off = 16; off; off >>= 1)
        #pragma unroll
        for (int n = 0; n < NOUT; n++)
            s[n] += __shfl_down_sync(0xffffffffu, s[n], off);

    if (lane == 0) {
        #pragma unroll
        for (int n = 0; n < NOUT; n++)
            out[(size_t)gw * NOUT + n] = tanhf(s[n] + bout[n]);   // MAX_OUTPUT = 1
    }
}

// ---------------------------------------------------------------------------
extern "C" void kernel_launch(void* const* d_in, const int* in_sizes, int n_in,
                              void* d_out, int out_size)
{
    const float* x    = (const float*)d_in[0];
    const float* W0   = (const float*)d_in[1];
    const float* b0   = (const float*)d_in[2];
    const float* Wh   = (const float*)d_in[3];
    const float* bh   = (const float*)d_in[4];
    const float* Wout = (const float*)d_in[5];
    const float* bout = (const float*)d_in[6];
    const float* la   = (const float*)d_in[7];
    const float* eps  = (const float*)d_in[8];
    float* out = (float*)d_out;

    z_kernel<<<1, 32>>>(la, eps);
    for (int k = 0; k < 5; k++) {
        dim3 grid(BATCH / BM, HID / BN, 5 - k);
        stage_kernel<<<grid, NTHREADS>>>(k, x, W0, b0, Wh, bh);
    }
    out_kernel<<<(BATCH * 32) / 256, 256>>>(Wout, bout, out);
}

// round 5
// speedup vs baseline: 1.0019x; 1.0019x over previous
#include <cuda_runtime.h>
#include <math.h>

#define BATCH   2048
#define IN_DIM  376
#define HID     1024
#define NOUT    17
#define NCELLS  6
#define NOPS    5

#define BM 128
#define BN 64
#define BK 16
#define TM 8
#define TN 4
#define NTHREADS 256

// scratch: acc buffers for nodes 1..5 (index i-1), plus softmax weights
__device__ float g_acc[5u * BATCH * HID];
__device__ float g_z[5 * 6 * 5];

typedef unsigned long long u64;

__device__ __forceinline__ u64 pack2(float lo, float hi) {
    u64 r; asm("mov.b64 %0, {%1, %2};" : "=l"(r) : "f"(lo), "f"(hi)); return r;
}
__device__ __forceinline__ void unpack2(u64 v, float& lo, float& hi) {
    asm("mov.b64 {%0, %1}, %2;" : "=f"(lo), "=f"(hi) : "l"(v));
}
// packed dual-FMA: (d.lo, d.hi) = (a.lo*b.lo+c.lo, a.hi*b.hi+c.hi)
__device__ __forceinline__ u64 ffma2(u64 a, u64 b, u64 c) {
    u64 d; asm("fma.rn.f32x2 %0, %1, %2, %3;" : "=l"(d) : "l"(a), "l"(b), "l"(c)); return d;
}

// ---------------------------------------------------------------------------
// z = softmax((log_alphas + eps) / TAU) over the op axis. TAU = 1.
// ---------------------------------------------------------------------------
__global__ void z_kernel(const float* __restrict__ la, const float* __restrict__ eps) {
    int t = threadIdx.x;
    if (t < 30) {
        const float* a = la  + t * NOPS;
        const float* e = eps + t * NOPS;
        float v[NOPS], mx = -1e30f;
        #pragma unroll
        for (int o = 0; o < NOPS; o++) { v[o] = a[o] + e[o]; mx = fmaxf(mx, v[o]); }
        float s = 0.f;
        #pragma unroll
        for (int o = 0; o < NOPS; o++) { v[o] = expf(v[o] - mx); s += v[o]; }
        float inv = 1.f / s;
        #pragma unroll
        for (int o = 0; o < NOPS; o++) g_z[t * NOPS + o] = v[o] * inv;
    }
}

// op order: 0=Tanh, 1=ReLU, 2=ELU, 3=LeakyReLU(0.01). Op 4 (NullOp) == 0, skipped.
__device__ __forceinline__ float actf(int o, float v) {
    switch (o) {
        case 0:  return tanhf(v);
        case 1:  return fmaxf(v, 0.f);
        case 2:  return v > 0.f ? v : expm1f(v);
        default: return v > 0.f ? v : 0.01f * v;
    }
}

// ---------------------------------------------------------------------------
// Stage kernel: source node `stage` feeds targets i = stage+1 .. 5.
// Each CTA: one (target, 128x64 tile); computes 4 op-GEMM tiles sharing the A
// tile, then epilogue: act + z-weight + accumulate into g_acc[target-1].
// grid = (BATCH/BM, HID/BN, 5-stage)
// ---------------------------------------------------------------------------
__global__ __launch_bounds__(NTHREADS, 1)
void stage_kernel(int stage, const float* __restrict__ x,
                  const float* __restrict__ W0, const float* __restrict__ b0,
                  const float* __restrict__ Wh, const float* __restrict__ bh)
{
    const int i = stage + 1 + blockIdx.z;   // target node (1..5)
    const float* A; int Kd;
    const float* W; const float* bias;
    if (stage == 0) {
        A = x; Kd = IN_DIM;
        W    = W0 + (size_t)(i * NOPS) * IN_DIM * HID;
        bias = b0 + (size_t)(i * NOPS) * HID;
    } else {
        A = g_acc + (size_t)(stage - 1) * BATCH * HID; Kd = HID;
        W    = Wh + (size_t)(((stage - 1) * NCELLS + i) * NOPS) * HID * HID;
        bias = bh + (size_t)(((stage - 1) * NCELLS + i) * NOPS) * HID;
    }
    float* accOut = g_acc + (size_t)(i - 1) * BATCH * HID;
    const float* zp = g_z + (stage * NCELLS + i) * NOPS;

    __shared__ __align__(16) float As[2][BK][BM];        // transposed A tile
    __shared__ __align__(16) float Bs[2][4][BK][BN];     // 4 op weight tiles

    const int tid = threadIdx.x;
    const int tx  = tid & 15;     // n micro index
    const int ty  = tid >> 4;     // m micro index
    const int bm0 = blockIdx.x * BM;
    const int bn0 = blockIdx.y * BN;

    u64 acc[4][TM][2];
    #pragma unroll
    for (int o = 0; o < 4; o++)
        #pragma unroll
        for (int m = 0; m < TM; m++) { acc[o][m][0] = 0ull; acc[o][m][1] = 0ull; }

    const int nk = (Kd + BK - 1) / BK;

    // global-load thread mapping
    const int ar  = tid >> 2;          // A: row 0..63 (+64 for second half)
    const int ac4 = (tid & 3) * 4;     // A: k offset within tile
    const int br  = tid >> 4;          // B: k row 0..15
    const int bn4 = (tid & 15) * 4;    // B: n offset

    float4 aR[2]; float4 bR[4];

    auto loadG = [&](int kt) {
        const int k0 = kt * BK;
        #pragma unroll
        for (int h = 0; h < 2; h++) {
            int row = ar + h * 64;
            int gk  = k0 + ac4;
            aR[h] = (gk + 4 <= Kd)
                ? *reinterpret_cast<const float4*>(A + (size_t)(bm0 + row) * Kd + gk)
                : make_float4(0.f, 0.f, 0.f, 0.f);
        }
        int gkb = k0 + br;
        #pragma unroll
        for (int o = 0; o < 4; o++) {
            bR[o] = (gkb < Kd)
                ? *reinterpret_cast<const float4*>(W + (size_t)o * Kd * HID + (size_t)gkb * HID + bn0 + bn4)
                : make_float4(0.f, 0.f, 0.f, 0.f);
        }
    };
    auto stS = [&](int buf) {
        #pragma unroll
        for (int h = 0; h < 2; h++) {
            int row = ar + h * 64;
            As[buf][ac4 + 0][row] = aR[h].x;
            As[buf][ac4 + 1][row] = aR[h].y;
            As[buf][ac4 + 2][row] = aR[h].z;
            As[buf][ac4 + 3][row] = aR[h].w;
        }
        #pragma unroll
        for (int o = 0; o < 4; o++)
            *reinterpret_cast<float4*>(&Bs[buf][o][br][bn4]) = bR[o];
    };

    loadG(0);
    stS(0);
    __syncthreads();

    for (int kt = 0; kt < nk; kt++) {
        const int cur = kt & 1;
        const bool more = (kt + 1 < nk);
        if (more) loadG(kt + 1);

        #pragma unroll
        for (int kk = 0; kk < BK; kk++) {
            float4 alo = *reinterpret_cast<const float4*>(&As[cur][kk][ty * TM]);
            float4 ahi = *reinterpret_cast<const float4*>(&As[cur][kk][ty * TM + 4]);
            u64 am[TM];
            am[0] = pack2(alo.x, alo.x); am[1] = pack2(alo.y, alo.y);
            am[2] = pack2(alo.z, alo.z); am[3] = pack2(alo.w, alo.w);
            am[4] = pack2(ahi.x, ahi.x); am[5] = pack2(ahi.y, ahi.y);
            am[6] = pack2(ahi.z, ahi.z); am[7] = pack2(ahi.w, ahi.w);
            #pragma unroll
            for (int o = 0; o < 4; o++) {
                const u64* bp = reinterpret_cast<const u64*>(&Bs[cur][o][kk][tx * TN]);
                u64 b01 = bp[0], b23 = bp[1];
                #pragma unroll
                for (int m = 0; m < TM; m++) {
                    acc[o][m][0] = ffma2(am[m], b01, acc[o][m][0]);
                    acc[o][m][1] = ffma2(am[m], b23, acc[o][m][1]);
                }
            }
        }
        if (more) { stS(cur ^ 1); __syncthreads(); }
    }

    // epilogue: bias + activation + z-weighted sum over ops, accumulate
    float zv[4];
    #pragma unroll
    for (int o = 0; o < 4; o++) zv[o] = zp[o];

    const int gn = bn0 + tx * TN;
    float4 bfr[4];
    #pragma unroll
    for (int o = 0; o < 4; o++)
        bfr[o] = *reinterpret_cast<const float4*>(bias + (size_t)o * HID + gn);

    #pragma unroll
    for (int m = 0; m < TM; m++) {
        const int gm = bm0 + ty * TM + m;
        float s0 = 0.f, s1 = 0.f, s2 = 0.f, s3 = 0.f;
        #pragma unroll
        for (int o = 0; o < 4; o++) {
            float p0, p1, p2, p3;
            unpack2(acc[o][m][0], p0, p1);
            unpack2(acc[o][m][1], p2, p3);
            p0 += bfr[o].x; p1 += bfr[o].y; p2 += bfr[o].z; p3 += bfr[o].w;
            s0 += zv[o] * actf(o, p0);
            s1 += zv[o] * actf(o, p1);
            s2 += zv[o] * actf(o, p2);
            s3 += zv[o] * actf(o, p3);
        }
        float* dst = accOut + (size_t)gm * HID + gn;
        float4 res = make_float4(s0, s1, s2, s3);
        if (stage != 0) {
            float4 old = *reinterpret_cast<const float4*>(dst);
            res.x += old.x; res.y += old.y; res.z += old.z; res.w += old.w;
        }
        *reinterpret_cast<float4*>(dst) = res;
    }
}

// ---------------------------------------------------------------------------
// out = tanh(acc5 @ Wout + bout); one warp per batch row, 17 outputs.
// ---------------------------------------------------------------------------
__global__ void out_kernel(const float* __restrict__ Wout,
                           const float* __restrict__ bout,
                           float* __restrict__ out)
{
    const int gw   = (blockIdx.x * blockDim.x + threadIdx.x) >> 5;
    const int lane = threadIdx.x & 31;
    if (gw >= BATCH) return;
    const float* a = g_acc + (size_t)4 * BATCH * HID + (size_t)gw * HID;

    float s[NOUT];
    #pragma unroll
    for (int n = 0; n < NOUT; n++) s[n] = 0.f;

    for (int kk = lane; kk < HID; kk += 32) {
        float av = a[kk];
        const float* wr = Wout + (size_t)kk * NOUT;
        #pragma unroll
        for (int n = 0; n < NOUT; n++) s[n] = fmaf(av, wr[n], s[n]);
    }
    #pragma unroll
    for (int off = 16; off; off >>= 1)
        #pragma unroll
        for (int n = 0; n < NOUT; n++)
            s[n] += __shfl_down_sync(0xffffffffu, s[n], off);

    if (lane == 0) {
        #pragma unroll
        for (int n = 0; n < NOUT; n++)
            out[(size_t)gw * NOUT + n] = tanhf(s[n] + bout[n]);   // MAX_OUTPUT = 1
    }
}

// ---------------------------------------------------------------------------
extern "C" void kernel_launch(void* const* d_in, const int* in_sizes, int n_in,
                              void* d_out, int out_size)
{
    const float* x    = (const float*)d_in[0];
    const float* W0   = (const float*)d_in[1];
    const float* b0   = (const float*)d_in[2];
    const float* Wh   = (const float*)d_in[3];
    const float* bh   = (const float*)d_in[4];
    const float* Wout = (const float*)d_in[5];
    const float* bout = (const float*)d_in[6];
    const float* la   = (const float*)d_in[7];
    const float* eps  = (const float*)d_in[8];
    float* out = (float*)d_out;

    z_kernel<<<1, 32>>>(la, eps);
    for (int k = 0; k < 5; k++) {
        dim3 grid(BATCH / BM, HID / BN, 5 - k);
        stage_kernel<<<grid, NTHREADS>>>(k, x, W0, b0, Wh, bh);
    }
    out_kernel<<<(BATCH * 32) / 256, 256>>>(Wout, bout, out);
}

// round 9
// speedup vs baseline: 1.7957x; 1.7923x over previous
#include <cuda_runtime.h>
#include <cuda_bf16.h>
#include <math.h>
#include <stdint.h>

#define BATCH   2048
#define IN_DIM  376
#define HID     1024
#define NOUT    17
#define NCELLS  6
#define NOPS    5
#define KP0     384            // IN_DIM padded to multiple of BK

#define BM 128
#define BN 32
#define BK 32
#define NTHREADS 256

// smem (u32 units): per buffer: A 2 planes x 128 rows x 20, B 8 (op,plane) x 32 x 20
#define A_ROW_STRIDE 20
#define A_PLANE      (128 * A_ROW_STRIDE)          // 2560 u32
#define B_TILE       (32 * A_ROW_STRIDE)           // 640 u32
#define BUF_U32      (2 * A_PLANE + 8 * B_TILE)    // 10240 u32 = 40 KB
#define OFF_B_U32    (2 * A_PLANE)
#define SMEM_BYTES   (2 * BUF_U32 * 4)             // 80 KB

// ---------------------------------------------------------------------------
// device scratch
// ---------------------------------------------------------------------------
__device__ float g_acc[5u * BATCH * HID];
__device__ float g_z[150];
// pre-split, transposed weights: [pair][n][k] bf16, k contiguous
__device__ __nv_bfloat16 g_wt0_hi[20u * HID * KP0];
__device__ __nv_bfloat16 g_wt0_lo[20u * HID * KP0];
__device__ __nv_bfloat16 g_wth_hi[40u * HID * HID];
__device__ __nv_bfloat16 g_wth_lo[40u * HID * HID];

// ---------------------------------------------------------------------------
__device__ __forceinline__ void bf16split(float a, __nv_bfloat16& hi, __nv_bfloat16& lo) {
    hi = __float2bfloat16_rn(a);
    lo = __float2bfloat16_rn(a - __bfloat162float(hi));
}
__device__ __forceinline__ uint32_t packbf2(__nv_bfloat16 a, __nv_bfloat16 b) {
    __nv_bfloat162 v(a, b);
    return *reinterpret_cast<uint32_t*>(&v);
}

__device__ __forceinline__ void mma16816(float* d, const uint32_t* a,
                                         uint32_t b0, uint32_t b1) {
    asm volatile(
        "mma.sync.aligned.m16n8k16.row.col.f32.bf16.bf16.f32 "
        "{%0,%1,%2,%3}, {%4,%5,%6,%7}, {%8,%9}, {%0,%1,%2,%3};\n"
        : "+f"(d[0]), "+f"(d[1]), "+f"(d[2]), "+f"(d[3])
        : "r"(a[0]), "r"(a[1]), "r"(a[2]), "r"(a[3]), "r"(b0), "r"(b1));
}

// ---------------------------------------------------------------------------
// z = softmax(log_alphas + eps) over op axis (TAU = 1)
// ---------------------------------------------------------------------------
__global__ void z_kernel(const float* __restrict__ la, const float* __restrict__ eps) {
    int t = threadIdx.x;
    if (t < 30) {
        float v[NOPS], mx = -1e30f;
        #pragma unroll
        for (int o = 0; o < NOPS; o++) { v[o] = la[t*NOPS+o] + eps[t*NOPS+o]; mx = fmaxf(mx, v[o]); }
        float s = 0.f;
        #pragma unroll
        for (int o = 0; o < NOPS; o++) { v[o] = expf(v[o] - mx); s += v[o]; }
        float inv = 1.f / s;
        #pragma unroll
        for (int o = 0; o < NOPS; o++) g_z[t*NOPS+o] = v[o] * inv;
    }
}

// ---------------------------------------------------------------------------
// Pre-pass: transpose + bf16-split weights into [pair][n][k] (k contiguous)
// ---------------------------------------------------------------------------
__global__ void split_t0_kernel(const float* __restrict__ W0) {
    __shared__ float t[32][33];
    const int pair = blockIdx.z;            // (i-1)*4 + op
    const int i = (pair >> 2) + 1, op = pair & 3;
    const float* src = W0 + ((size_t)(i * NOPS + op)) * IN_DIM * HID;
    const int kb = blockIdx.x * 32, nb = blockIdx.y * 32;
    const int tx = threadIdx.x, ty = threadIdx.y;       // (32, 8)
    #pragma unroll
    for (int r = 0; r < 4; r++) {
        int k = kb + ty * 4 + r;
        t[ty*4+r][tx] = (k < IN_DIM) ? src[(size_t)k * HID + nb + tx] : 0.f;
    }
    __syncthreads();
    __nv_bfloat16* dh = g_wt0_hi + (size_t)pair * HID * KP0;
    __nv_bfloat16* dl = g_wt0_lo + (size_t)pair * HID * KP0;
    #pragma unroll
    for (int r = 0; r < 4; r++) {
        int n = nb + ty * 4 + r, k = kb + tx;
        __nv_bfloat16 hi, lo; bf16split(t[tx][ty*4+r], hi, lo);
        dh[(size_t)n * KP0 + k] = hi;
        dl[(size_t)n * KP0 + k] = lo;
    }
}

__global__ void split_th_kernel(const float* __restrict__ Wh) {
    __shared__ float t[32][33];
    const int pair = blockIdx.z;            // e*4 + op
    const int e = pair >> 2, op = pair & 3;
    int s, i;
    if      (e < 4) { s = 1; i = e + 2; }
    else if (e < 7) { s = 2; i = e - 4 + 3; }
    else if (e < 9) { s = 3; i = e - 7 + 4; }
    else            { s = 4; i = 5; }
    const float* src = Wh + ((size_t)(((s-1) * NCELLS + i) * NOPS + op)) * HID * HID;
    const int kb = blockIdx.x * 32, nb = blockIdx.y * 32;
    const int tx = threadIdx.x, ty = threadIdx.y;
    #pragma unroll
    for (int r = 0; r < 4; r++)
        t[ty*4+r][tx] = src[(size_t)(kb + ty*4 + r) * HID + nb + tx];
    __syncthreads();
    __nv_bfloat16* dh = g_wth_hi + (size_t)pair * HID * HID;
    __nv_bfloat16* dl = g_wth_lo + (size_t)pair * HID * HID;
    #pragma unroll
    for (int r = 0; r < 4; r++) {
        int n = nb + ty * 4 + r, k = kb + tx;
        __nv_bfloat16 hi, lo; bf16split(t[tx][ty*4+r], hi, lo);
        dh[(size_t)n * HID + k] = hi;
        dl[(size_t)n * HID + k] = lo;
    }
}

// ---------------------------------------------------------------------------
// Stage GEMM: bf16x3 mma.sync. CTA = [128 x 32] x 4 ops; warp = 32x16.
// grid = (BATCH/BM, HID/BN, 5-stage)
// ---------------------------------------------------------------------------
__global__ __launch_bounds__(NTHREADS)
void stage_mma_kernel(int stage, const float* __restrict__ x,
                      const float* __restrict__ b0, const float* __restrict__ bh)
{
    extern __shared__ uint32_t smem[];
    const int tid = threadIdx.x;
    const int i   = stage + 1 + blockIdx.z;
    const int bm0 = blockIdx.x * BM;
    const int bn0 = blockIdx.y * BN;

    const float* A; const __nv_bfloat16 *Bhi, *Blo; const float* bias;
    int Kd, Kp;
    if (stage == 0) {
        A = x; Kd = IN_DIM; Kp = KP0;
        const size_t pb = (size_t)((i - 1) * 4) * HID * KP0;
        Bhi = g_wt0_hi + pb; Blo = g_wt0_lo + pb;
        bias = b0 + (size_t)(i * NOPS) * HID;
    } else {
        A = g_acc + (size_t)(stage - 1) * BATCH * HID; Kd = HID; Kp = HID;
        static const int eoff[5] = {0, 0, 4, 7, 9};
        const int e = eoff[stage] + (i - stage - 1);
        const size_t pb = (size_t)(e * 4) * HID * HID;
        Bhi = g_wth_hi + pb; Blo = g_wth_lo + pb;
        bias = bh + (size_t)(((stage - 1) * NCELLS + i) * NOPS) * HID;
    }
    float* accOut = g_acc + (size_t)(i - 1) * BATCH * HID;
    const float* zp = g_z + (stage * NCELLS + i) * NOPS;

    const int w    = tid >> 5, lane = tid & 31;
    const int wm   = (w & 3) * 32;          // warp M offset
    const int wn   = (w >> 2) * 16;         // warp N offset
    const int qr   = lane >> 2;             // t/4
    const int qk   = lane & 3;              // t%4

    float acc[4][2][2][4];                  // [op][mf][nf][c]
    #pragma unroll
    for (int o = 0; o < 4; o++)
        #pragma unroll
        for (int mf = 0; mf < 2; mf++)
            #pragma unroll
            for (int nf = 0; nf < 2; nf++)
                #pragma unroll
                for (int c = 0; c < 4; c++) acc[o][mf][nf][c] = 0.f;

    const int nk = Kp / BK;

    // ---- producer regs ----
    float4 aR[4];            // A: row tid/2, half tid&1 -> 4 float4 (16 fp32)
    uint4  bR[4];            // B: 4 uint4
    const int arow = tid >> 1, ahalf = tid & 1;

    auto loadG = [&](int kt) {
        const int k0 = kt * BK + ahalf * 16;
        #pragma unroll
        for (int q = 0; q < 4; q++) {
            const int gk = k0 + q * 4;
            aR[q] = (gk < Kd)
                ? *reinterpret_cast<const float4*>(A + (size_t)(bm0 + arow) * Kd + gk)
                : make_float4(0.f, 0.f, 0.f, 0.f);
        }
        #pragma unroll
        for (int q = 0; q < 4; q++) {
            const int lin  = q * 256 + tid;       // 0..1023
            const int tile = lin >> 7;            // (op,plane) 0..7
            const int rem  = lin & 127;
            const int n    = rem >> 2, q4 = rem & 3;
            const __nv_bfloat16* src = (tile & 1) ? Blo : Bhi;
            src += (size_t)(tile >> 1) * HID * Kp;
            bR[q] = *reinterpret_cast<const uint4*>(
                src + (size_t)(bn0 + n) * Kp + kt * BK + q4 * 8);
        }
    };
    auto stS = [&](int buf) {
        uint32_t* base = smem + buf * BUF_U32;
        // A: convert fp32 -> bf16 hi/lo pairs
        {
            uint32_t* ah = base;
            uint32_t* al = base + A_PLANE;
            #pragma unroll
            for (int q = 0; q < 4; q++) {
                __nv_bfloat16 hx, lx, hy, ly, hz, lz, hw, lw;
                bf16split(aR[q].x, hx, lx); bf16split(aR[q].y, hy, ly);
                bf16split(aR[q].z, hz, lz); bf16split(aR[q].w, hw, lw);
                const int idx = arow * A_ROW_STRIDE + ahalf * 8 + q * 2;
                ah[idx]     = packbf2(hx, hy);
                ah[idx + 1] = packbf2(hz, hw);
                al[idx]     = packbf2(lx, ly);
                al[idx + 1] = packbf2(lz, lw);
            }
        }
        // B: straight copy (already bf16)
        {
            uint32_t* bb = base + OFF_B_U32;
            #pragma unroll
            for (int q = 0; q < 4; q++) {
                const int lin  = q * 256 + tid;
                const int tile = lin >> 7;
                const int rem  = lin & 127;
                const int n    = rem >> 2, q4 = rem & 3;
                *reinterpret_cast<uint4*>(bb + tile * B_TILE + n * A_ROW_STRIDE + q4 * 4) = bR[q];
            }
        }
    };

    loadG(0);
    stS(0);
    __syncthreads();

    for (int kt = 0; kt < nk; kt++) {
        const int cur  = kt & 1;
        const bool more = (kt + 1 < nk);
        if (more) loadG(kt + 1);

        const uint32_t* base = smem + cur * BUF_U32;
        #pragma unroll
        for (int kp = 0; kp < 2; kp++) {
            // A fragments: [plane][mf][4]
            // a0: k word qk       (k = qk*2, qk*2+1),   row qr
            // a1: same k word,    row qr+8
            // a2: k word qk + 4   (k = qk*2+8, +9),     row qr
            // a3: k word qk + 4,  row qr+8
            uint32_t afr[2][2][4];
            #pragma unroll
            for (int pl = 0; pl < 2; pl++) {
                const uint32_t* ap = base + pl * A_PLANE;
                #pragma unroll
                for (int mf = 0; mf < 2; mf++) {
                    const int idx = (wm + mf * 16 + qr) * A_ROW_STRIDE + kp * 8 + qk;
                    afr[pl][mf][0] = ap[idx];
                    afr[pl][mf][1] = ap[idx + 8 * A_ROW_STRIDE];
                    afr[pl][mf][2] = ap[idx + 4];
                    afr[pl][mf][3] = ap[idx + 8 * A_ROW_STRIDE + 4];
                }
            }
            #pragma unroll
            for (int op = 0; op < 4; op++) {
                uint32_t bfrg[2][2][2];   // [plane][nf][reg]
                #pragma unroll
                for (int pl = 0; pl < 2; pl++) {
                    const uint32_t* bp = base + OFF_B_U32 + (op * 2 + pl) * B_TILE;
                    #pragma unroll
                    for (int nf = 0; nf < 2; nf++) {
                        const int idx = (wn + nf * 8 + qr) * A_ROW_STRIDE + kp * 8 + qk;
                        bfrg[pl][nf][0] = bp[idx];
                        bfrg[pl][nf][1] = bp[idx + 4];
                    }
                }
                #pragma unroll
                for (int mf = 0; mf < 2; mf++)
                    #pragma unroll
                    for (int nf = 0; nf < 2; nf++) {
                        float* d = acc[op][mf][nf];
                        mma16816(d, afr[0][mf], bfrg[0][nf][0], bfrg[0][nf][1]); // hi*hi
                        mma16816(d, afr[0][mf], bfrg[1][nf][0], bfrg[1][nf][1]); // hi*lo
                        mma16816(d, afr[1][mf], bfrg[0][nf][0], bfrg[0][nf][1]); // lo*hi
                    }
            }
        }
        if (more) { __syncthreads(); stS(cur ^ 1); __syncthreads(); }
    }

    // ---- epilogue: bias + act + z-weighted op-sum, RMW into g_acc ----
    const float z0 = zp[0], z1 = zp[1], z2 = zp[2], z3 = zp[3];
    #pragma unroll
    for (int mf = 0; mf < 2; mf++)
        #pragma unroll
        for (int nf = 0; nf < 2; nf++) {
            const int n0 = bn0 + wn + nf * 8 + qk * 2;
            float bv[4][2];
            #pragma unroll
            for (int op = 0; op < 4; op++) {
                bv[op][0] = bias[op * HID + n0];
                bv[op][1] = bias[op * HID + n0 + 1];
            }
            #pragma unroll
            for (int half = 0; half < 2; half++) {
                const int m = bm0 + wm + mf * 16 + qr + half * 8;
                float r0 = 0.f, r1 = 0.f;
                #pragma unroll
                for (int op = 0; op < 4; op++) {
                    const float p0 = acc[op][mf][nf][half * 2 + 0] + bv[op][0];
                    const float p1 = acc[op][mf][nf][half * 2 + 1] + bv[op][1];
                    float a0, a1;
                    switch (op) {
                        case 0:  a0 = tanhf(p0);                      a1 = tanhf(p1);                      break;
                        case 1:  a0 = fmaxf(p0, 0.f);                 a1 = fmaxf(p1, 0.f);                 break;
                        case 2:  a0 = p0 > 0.f ? p0 : expm1f(p0);     a1 = p1 > 0.f ? p1 : expm1f(p1);     break;
                        default: a0 = p0 > 0.f ? p0 : 0.01f * p0;     a1 = p1 > 0.f ? p1 : 0.01f * p1;     break;
                    }
                    const float zv = (op == 0) ? z0 : (op == 1) ? z1 : (op == 2) ? z2 : z3;
                    r0 += zv * a0; r1 += zv * a1;
                }
                float* dst = accOut + (size_t)m * HID + n0;
                if (stage != 0) {
                    float2 old = *reinterpret_cast<const float2*>(dst);
                    r0 += old.x; r1 += old.y;
                }
                float2 res; res.x = r0; res.y = r1;
                *reinterpret_cast<float2*>(dst) = res;
            }
        }
}

// ---------------------------------------------------------------------------
// out = tanh(acc5 @ Wout + bout)
// ---------------------------------------------------------------------------
__global__ void out_kernel(const float* __restrict__ Wout,
                           const float* __restrict__ bout,
                           float* __restrict__ out)
{
    const int gw   = (blockIdx.x * blockDim.x + threadIdx.x) >> 5;
    const int lane = threadIdx.x & 31;
    if (gw >= BATCH) return;
    const float* a = g_acc + (size_t)4 * BATCH * HID + (size_t)gw * HID;

    float s[NOUT];
    #pragma unroll
    for (int n = 0; n < NOUT; n++) s[n] = 0.f;
    for (int kk = lane; kk < HID; kk += 32) {
        const float av = a[kk];
        const float* wr = Wout + (size_t)kk * NOUT;
        #pragma unroll
        for (int n = 0; n < NOUT; n++) s[n] = fmaf(av, wr[n], s[n]);
    }
    #pragma unroll
    for (int off = 16; off; off >>= 1)
        #pragma unroll
        for (int n = 0; n < NOUT; n++)
            s[n] += __shfl_down_sync(0xffffffffu, s[n], off);
    if (lane == 0) {
        #pragma unroll
        for (int n = 0; n < NOUT; n++)
            out[(size_t)gw * NOUT + n] = tanhf(s[n] + bout[n]);
    }
}

// ---------------------------------------------------------------------------
extern "C" void kernel_launch(void* const* d_in, const int* in_sizes, int n_in,
                              void* d_out, int out_size)
{
    const float* x    = (const float*)d_in[0];
    const float* W0   = (const float*)d_in[1];
    const float* b0   = (const float*)d_in[2];
    const float* Wh   = (const float*)d_in[3];
    const float* bh   = (const float*)d_in[4];
    const float* Wout = (const float*)d_in[5];
    const float* bout = (const float*)d_in[6];
    const float* la   = (const float*)d_in[7];
    const float* eps  = (const float*)d_in[8];
    float* out = (float*)d_out;

    cudaFuncSetAttribute(stage_mma_kernel,
                         cudaFuncAttributeMaxDynamicSharedMemorySize, SMEM_BYTES);

    z_kernel<<<1, 32>>>(la, eps);
    split_t0_kernel<<<dim3(KP0 / 32, HID / 32, 20), dim3(32, 8)>>>(W0);
    split_th_kernel<<<dim3(HID / 32, HID / 32, 40), dim3(32, 8)>>>(Wh);
    for (int k = 0; k < 5; k++) {
        dim3 grid(BATCH / BM, HID / BN, 5 - k);
        stage_mma_kernel<<<grid, NTHREADS, SMEM_BYTES>>>(k, x, b0, bh);
    }
    out_kernel<<<(BATCH * 32) / 256, 256>>>(Wout, bout, out);
}

// round 10
// speedup vs baseline: 1.8218x; 1.0146x over previous
#include <cuda_runtime.h>
#include <cuda_bf16.h>
#include <math.h>
#include <stdint.h>

#define BATCH   2048
#define IN_DIM  376
#define HID     1024
#define NOUT    17
#define NCELLS  6
#define NOPS    5
#define KP0     384            // IN_DIM padded to multiple of BK

#define BM 128
#define BN 32
#define BK 32
#define NTHREADS 256

// smem (u32 units): per buffer: A 2 planes x 128 rows x 20, B 8 (op,plane) x 32 x 20
#define A_ROW_STRIDE 20
#define A_PLANE      (128 * A_ROW_STRIDE)          // 2560 u32
#define B_TILE       (32 * A_ROW_STRIDE)           // 640 u32
#define BUF_U32      (2 * A_PLANE + 8 * B_TILE)    // 10240 u32 = 40 KB
#define OFF_B_U32    (2 * A_PLANE)
#define SMEM_BYTES   (2 * BUF_U32 * 4)             // 80 KB

// ---------------------------------------------------------------------------
// device scratch
// ---------------------------------------------------------------------------
__device__ float g_acc[5u * BATCH * HID];
__device__ float g_z[150];
// pre-split, transposed weights: [pair][n][k] bf16, k contiguous
__device__ __nv_bfloat16 g_wt0_hi[20u * HID * KP0];
__device__ __nv_bfloat16 g_wt0_lo[20u * HID * KP0];
__device__ __nv_bfloat16 g_wth_hi[40u * HID * HID];
__device__ __nv_bfloat16 g_wth_lo[40u * HID * HID];

// ---------------------------------------------------------------------------
__device__ __forceinline__ void bf16split(float a, __nv_bfloat16& hi, __nv_bfloat16& lo) {
    hi = __float2bfloat16_rn(a);
    lo = __float2bfloat16_rn(a - __bfloat162float(hi));
}
__device__ __forceinline__ uint32_t packbf2(__nv_bfloat16 a, __nv_bfloat16 b) {
    __nv_bfloat162 v(a, b);
    return *reinterpret_cast<uint32_t*>(&v);
}
__device__ __forceinline__ uint32_t smem_u32(const void* p) {
    uint32_t a;
    asm("{ .reg .u64 t; cvta.to.shared.u64 t, %1; cvt.u32.u64 %0, t; }"
        : "=r"(a) : "l"(p));
    return a;
}
__device__ __forceinline__ void ldmx4(uint32_t* r, uint32_t addr) {
    asm volatile("ldmatrix.sync.aligned.m8n8.x4.shared.b16 {%0,%1,%2,%3}, [%4];"
        : "=r"(r[0]), "=r"(r[1]), "=r"(r[2]), "=r"(r[3]) : "r"(addr));
}
__device__ __forceinline__ void cp16(uint32_t dst, const void* src) {
    asm volatile("cp.async.cg.shared.global [%0], [%1], 16;" :: "r"(dst), "l"(src));
}
__device__ __forceinline__ void cp_commit() { asm volatile("cp.async.commit_group;"); }
__device__ __forceinline__ void cp_wait0()  { asm volatile("cp.async.wait_group 0;" ::: "memory"); }

__device__ __forceinline__ void mma16816(float* d, const uint32_t* a,
                                         uint32_t b0, uint32_t b1) {
    asm volatile(
        "mma.sync.aligned.m16n8k16.row.col.f32.bf16.bf16.f32 "
        "{%0,%1,%2,%3}, {%4,%5,%6,%7}, {%8,%9}, {%0,%1,%2,%3};\n"
        : "+f"(d[0]), "+f"(d[1]), "+f"(d[2]), "+f"(d[3])
        : "r"(a[0]), "r"(a[1]), "r"(a[2]), "r"(a[3]), "r"(b0), "r"(b1));
}

// ---------------------------------------------------------------------------
// z = softmax(log_alphas + eps) over op axis (TAU = 1)
// ---------------------------------------------------------------------------
__global__ void z_kernel(const float* __restrict__ la, const float* __restrict__ eps) {
    int t = threadIdx.x;
    if (t < 30) {
        float v[NOPS], mx = -1e30f;
        #pragma unroll
        for (int o = 0; o < NOPS; o++) { v[o] = la[t*NOPS+o] + eps[t*NOPS+o]; mx = fmaxf(mx, v[o]); }
        float s = 0.f;
        #pragma unroll
        for (int o = 0; o < NOPS; o++) { v[o] = expf(v[o] - mx); s += v[o]; }
        float inv = 1.f / s;
        #pragma unroll
        for (int o = 0; o < NOPS; o++) g_z[t*NOPS+o] = v[o] * inv;
    }
}

// ---------------------------------------------------------------------------
// Pre-pass: transpose + bf16-split weights into [pair][n][k] (k contiguous)
// ---------------------------------------------------------------------------
__global__ void split_t0_kernel(const float* __restrict__ W0) {
    __shared__ float t[32][33];
    const int pair = blockIdx.z;            // (i-1)*4 + op
    const int i = (pair >> 2) + 1, op = pair & 3;
    const float* src = W0 + ((size_t)(i * NOPS + op)) * IN_DIM * HID;
    const int kb = blockIdx.x * 32, nb = blockIdx.y * 32;
    const int tx = threadIdx.x, ty = threadIdx.y;       // (32, 8)
    #pragma unroll
    for (int r = 0; r < 4; r++) {
        int k = kb + ty * 4 + r;
        t[ty*4+r][tx] = (k < IN_DIM) ? src[(size_t)k * HID + nb + tx] : 0.f;
    }
    __syncthreads();
    __nv_bfloat16* dh = g_wt0_hi + (size_t)pair * HID * KP0;
    __nv_bfloat16* dl = g_wt0_lo + (size_t)pair * HID * KP0;
    #pragma unroll
    for (int r = 0; r < 4; r++) {
        int n = nb + ty * 4 + r, k = kb + tx;
        __nv_bfloat16 hi, lo; bf16split(t[tx][ty*4+r], hi, lo);
        dh[(size_t)n * KP0 + k] = hi;
        dl[(size_t)n * KP0 + k] = lo;
    }
}

__global__ void split_th_kernel(const float* __restrict__ Wh) {
    __shared__ float t[32][33];
    const int pair = blockIdx.z;            // e*4 + op
    const int e = pair >> 2, op = pair & 3;
    int s, i;
    if      (e < 4) { s = 1; i = e + 2; }
    else if (e < 7) { s = 2; i = e - 4 + 3; }
    else if (e < 9) { s = 3; i = e - 7 + 4; }
    else            { s = 4; i = 5; }
    const float* src = Wh + ((size_t)(((s-1) * NCELLS + i) * NOPS + op)) * HID * HID;
    const int kb = blockIdx.x * 32, nb = blockIdx.y * 32;
    const int tx = threadIdx.x, ty = threadIdx.y;
    #pragma unroll
    for (int r = 0; r < 4; r++)
        t[ty*4+r][tx] = src[(size_t)(kb + ty*4 + r) * HID + nb + tx];
    __syncthreads();
    __nv_bfloat16* dh = g_wth_hi + (size_t)pair * HID * HID;
    __nv_bfloat16* dl = g_wth_lo + (size_t)pair * HID * HID;
    #pragma unroll
    for (int r = 0; r < 4; r++) {
        int n = nb + ty * 4 + r, k = kb + tx;
        __nv_bfloat16 hi, lo; bf16split(t[tx][ty*4+r], hi, lo);
        dh[(size_t)n * HID + k] = hi;
        dl[(size_t)n * HID + k] = lo;
    }
}

// ---------------------------------------------------------------------------
// Stage GEMM: bf16x3 mma.sync + ldmatrix + cp.async(B).
// CTA = [128 x 32] x 4 ops; warp = 32x16. grid = (BATCH/BM, HID/BN, 5-stage)
// ---------------------------------------------------------------------------
__global__ __launch_bounds__(NTHREADS)
void stage_mma_kernel(int stage, const float* __restrict__ x,
                      const float* __restrict__ b0, const float* __restrict__ bh)
{
    extern __shared__ uint32_t smem[];
    const uint32_t sbase = smem_u32(smem);
    const int tid = threadIdx.x;
    const int i   = stage + 1 + blockIdx.z;
    const int bm0 = blockIdx.x * BM;
    const int bn0 = blockIdx.y * BN;

    const float* A; const __nv_bfloat16 *Bhi, *Blo; const float* bias;
    int Kd, Kp;
    if (stage == 0) {
        A = x; Kd = IN_DIM; Kp = KP0;
        const size_t pb = (size_t)((i - 1) * 4) * HID * KP0;
        Bhi = g_wt0_hi + pb; Blo = g_wt0_lo + pb;
        bias = b0 + (size_t)(i * NOPS) * HID;
    } else {
        A = g_acc + (size_t)(stage - 1) * BATCH * HID; Kd = HID; Kp = HID;
        static const int eoff[5] = {0, 0, 4, 7, 9};
        const int e = eoff[stage] + (i - stage - 1);
        const size_t pb = (size_t)(e * 4) * HID * HID;
        Bhi = g_wth_hi + pb; Blo = g_wth_lo + pb;
        bias = bh + (size_t)(((stage - 1) * NCELLS + i) * NOPS) * HID;
    }
    float* accOut = g_acc + (size_t)(i - 1) * BATCH * HID;
    const float* zp = g_z + (stage * NCELLS + i) * NOPS;

    const int w    = tid >> 5, lane = tid & 31;
    const int wm   = (w & 3) * 32;          // warp M offset
    const int wn   = (w >> 2) * 16;         // warp N offset
    const int qr   = lane >> 2;             // t/4
    const int qk   = lane & 3;              // t%4
    const int lg   = lane >> 3;             // ldmatrix group 0..3
    const int lr   = lane & 7;              // ldmatrix row in group

    // ldmatrix per-lane byte offsets (within a plane/tile)
    // A x4 tiles: {m0-7,k0-7},{m8-15,k0-7},{m0-7,k8-15},{m8-15,k8-15}
    const uint32_t aoff = ((wm + (lg & 1) * 8 + lr) * A_ROW_STRIDE + (lg >> 1) * 4) * 4;
    // B x4 tiles: {n0-7,b0},{n0-7,b1},{n8-15,b0},{n8-15,b1}
    const uint32_t boff = ((wn + (lg >> 1) * 8 + lr) * A_ROW_STRIDE + (lg & 1) * 4) * 4;

    float acc[4][2][2][4];                  // [op][mf][nf][c]
    #pragma unroll
    for (int o = 0; o < 4; o++)
        #pragma unroll
        for (int mf = 0; mf < 2; mf++)
            #pragma unroll
            for (int nf = 0; nf < 2; nf++)
                #pragma unroll
                for (int c = 0; c < 4; c++) acc[o][mf][nf][c] = 0.f;

    const int nk = Kp / BK;

    // ---- producers ----
    float4 aR[4];            // A: row tid/2, half tid&1 -> 4 float4 (16 fp32)
    const int arow = tid >> 1, ahalf = tid & 1;

    // B cp.async per-thread mapping (4 chunks of 16B)
    const int btile = tid >> 6;                       // base tile pair idx helper
    auto loadA = [&](int kt) {
        const int k0 = kt * BK + ahalf * 16;
        #pragma unroll
        for (int q = 0; q < 4; q++) {
            const int gk = k0 + q * 4;
            aR[q] = (gk < Kd)
                ? *reinterpret_cast<const float4*>(A + (size_t)(bm0 + arow) * Kd + gk)
                : make_float4(0.f, 0.f, 0.f, 0.f);
        }
    };
    auto cpB = [&](int kt, int buf) {
        uint32_t bb = sbase + (buf * BUF_U32 + OFF_B_U32) * 4;
        #pragma unroll
        for (int q = 0; q < 4; q++) {
            const int lin  = q * 256 + tid;       // 0..1023
            const int tile = lin >> 7;            // (op,plane) 0..7
            const int rem  = lin & 127;
            const int n    = rem >> 2, q4 = rem & 3;
            const __nv_bfloat16* src = (tile & 1) ? Blo : Bhi;
            src += (size_t)(tile >> 1) * HID * Kp + (size_t)(bn0 + n) * Kp + kt * BK + q4 * 8;
            cp16(bb + (tile * B_TILE + n * A_ROW_STRIDE + q4 * 4) * 4, src);
        }
    };
    auto stA = [&](int buf) {
        uint32_t* base = smem + buf * BUF_U32;
        uint32_t* ah = base;
        uint32_t* al = base + A_PLANE;
        #pragma unroll
        for (int q = 0; q < 4; q++) {
            __nv_bfloat16 hx, lx, hy, ly, hz, lz, hw, lw;
            bf16split(aR[q].x, hx, lx); bf16split(aR[q].y, hy, ly);
            bf16split(aR[q].z, hz, lz); bf16split(aR[q].w, hw, lw);
            const int idx = arow * A_ROW_STRIDE + ahalf * 8 + q * 2;
            ah[idx]     = packbf2(hx, hy);
            ah[idx + 1] = packbf2(hz, hw);
            al[idx]     = packbf2(lx, ly);
            al[idx + 1] = packbf2(lz, lw);
        }
    };

    loadA(0);
    cpB(0, 0);
    cp_commit();
    stA(0);
    cp_wait0();
    __syncthreads();

    for (int kt = 0; kt < nk; kt++) {
        const int cur  = kt & 1;
        const bool more = (kt + 1 < nk);
        if (more) {
            cpB(kt + 1, cur ^ 1);
            cp_commit();
            loadA(kt + 1);
        }

        const uint32_t bufA = sbase + (cur * BUF_U32) * 4;
        const uint32_t bufB = sbase + (cur * BUF_U32 + OFF_B_U32) * 4;
        #pragma unroll
        for (int kp = 0; kp < 2; kp++) {
            uint32_t afr[2][2][4];    // [plane][mf][a0..a3]
            #pragma unroll
            for (int pl = 0; pl < 2; pl++)
                #pragma unroll
                for (int mf = 0; mf < 2; mf++)
                    ldmx4(afr[pl][mf],
                          bufA + pl * (A_PLANE * 4) + aoff + mf * (16 * A_ROW_STRIDE * 4) + kp * 32);
            #pragma unroll
            for (int op = 0; op < 4; op++) {
                uint32_t bfrg[2][4];  // [plane][nf0b0, nf0b1, nf1b0, nf1b1]
                #pragma unroll
                for (int pl = 0; pl < 2; pl++)
                    ldmx4(bfrg[pl],
                          bufB + (op * 2 + pl) * (B_TILE * 4) + boff + kp * 32);
                #pragma unroll
                for (int mf = 0; mf < 2; mf++)
                    #pragma unroll
                    for (int nf = 0; nf < 2; nf++) {
                        float* d = acc[op][mf][nf];
                        mma16816(d, afr[0][mf], bfrg[0][nf*2], bfrg[0][nf*2+1]); // hi*hi
                        mma16816(d, afr[0][mf], bfrg[1][nf*2], bfrg[1][nf*2+1]); // hi*lo
                        mma16816(d, afr[1][mf], bfrg[0][nf*2], bfrg[0][nf*2+1]); // lo*hi
                    }
            }
        }
        if (more) {
            __syncthreads();
            stA(cur ^ 1);
            cp_wait0();
            __syncthreads();
        }
    }

    // ---- epilogue: bias + act + z-weighted op-sum, RMW into g_acc ----
    const float z0 = zp[0], z1 = zp[1], z2 = zp[2], z3 = zp[3];
    #pragma unroll
    for (int mf = 0; mf < 2; mf++)
        #pragma unroll
        for (int nf = 0; nf < 2; nf++) {
            const int n0 = bn0 + wn + nf * 8 + qk * 2;
            float bv[4][2];
            #pragma unroll
            for (int op = 0; op < 4; op++) {
                bv[op][0] = bias[op * HID + n0];
                bv[op][1] = bias[op * HID + n0 + 1];
            }
            #pragma unroll
            for (int half = 0; half < 2; half++) {
                const int m = bm0 + wm + mf * 16 + qr + half * 8;
                float r0 = 0.f, r1 = 0.f;
                #pragma unroll
                for (int op = 0; op < 4; op++) {
                    const float p0 = acc[op][mf][nf][half * 2 + 0] + bv[op][0];
                    const float p1 = acc[op][mf][nf][half * 2 + 1] + bv[op][1];
                    float a0, a1;
                    switch (op) {
                        case 0:  a0 = tanhf(p0);                      a1 = tanhf(p1);                      break;
                        case 1:  a0 = fmaxf(p0, 0.f);                 a1 = fmaxf(p1, 0.f);                 break;
                        case 2:  a0 = p0 > 0.f ? p0 : expm1f(p0);     a1 = p1 > 0.f ? p1 : expm1f(p1);     break;
                        default: a0 = p0 > 0.f ? p0 : 0.01f * p0;     a1 = p1 > 0.f ? p1 : 0.01f * p1;     break;
                    }
                    const float zv = (op == 0) ? z0 : (op == 1) ? z1 : (op == 2) ? z2 : z3;
                    r0 += zv * a0; r1 += zv * a1;
                }
                float* dst = accOut + (size_t)m * HID + n0;
                if (stage != 0) {
                    float2 old = *reinterpret_cast<const float2*>(dst);
                    r0 += old.x; r1 += old.y;
                }
                float2 res; res.x = r0; res.y = r1;
                *reinterpret_cast<float2*>(dst) = res;
            }
        }
}

// ---------------------------------------------------------------------------
// out = tanh(acc5 @ Wout + bout)
// ---------------------------------------------------------------------------
__global__ void out_kernel(const float* __restrict__ Wout,
                           const float* __restrict__ bout,
                           float* __restrict__ out)
{
    const int gw   = (blockIdx.x * blockDim.x + threadIdx.x) >> 5;
    const int lane = threadIdx.x & 31;
    if (gw >= BATCH) return;
    const float* a = g_acc + (size_t)4 * BATCH * HID + (size_t)gw * HID;

    float s[NOUT];
    #pragma unroll
    for (int n = 0; n < NOUT; n++) s[n] = 0.f;
    for (int kk = lane; kk < HID; kk += 32) {
        const float av = a[kk];
        const float* wr = Wout + (size_t)kk * NOUT;
        #pragma unroll
        for (int n = 0; n < NOUT; n++) s[n] = fmaf(av, wr[n], s[n]);
    }
    #pragma unroll
    for (int off = 16; off; off >>= 1)
        #pragma unroll
        for (int n = 0; n < NOUT; n++)
            s[n] += __shfl_down_sync(0xffffffffu, s[n], off);
    if (lane == 0) {
        #pragma unroll
        for (int n = 0; n < NOUT; n++)
            out[(size_t)gw * NOUT + n] = tanhf(s[n] + bout[n]);
    }
}

// ---------------------------------------------------------------------------
extern "C" void kernel_launch(void* const* d_in, const int* in_sizes, int n_in,
                              void* d_out, int out_size)
{
    const float* x    = (const float*)d_in[0];
    const float* W0   = (const float*)d_in[1];
    const float* b0   = (const float*)d_in[2];
    const float* Wh   = (const float*)d_in[3];
    const float* bh   = (const float*)d_in[4];
    const float* Wout = (const float*)d_in[5];
    const float* bout = (const float*)d_in[6];
    const float* la   = (const float*)d_in[7];
    const float* eps  = (const float*)d_in[8];
    float* out = (float*)d_out;

    cudaFuncSetAttribute(stage_mma_kernel,
                         cudaFuncAttributeMaxDynamicSharedMemorySize, SMEM_BYTES);

    z_kernel<<<1, 32>>>(la, eps);
    split_t0_kernel<<<dim3(KP0 / 32, HID / 32, 20), dim3(32, 8)>>>(W0);
    split_th_kernel<<<dim3(HID / 32, HID / 32, 40), dim3(32, 8)>>>(Wh);
    for (int k = 0; k < 5; k++) {
        dim3 grid(BATCH / BM, HID / BN, 5 - k);
        stage_mma_kernel<<<grid, NTHREADS, SMEM_BYTES>>>(k, x, b0, bh);
    }
    out_kernel<<<(BATCH * 32) / 256, 256>>>(Wout, bout, out);
}